// round 9
// baseline (speedup 1.0000x reference)
#include <cuda_runtime.h>
#include <cstdint>

#define DDIM   4096
#define M_ROWS 8192
#define N_ROWS 4096
#define KINT   (DDIM / 4)          // 1024 ints per row

__device__ __align__(256) int8_t g_qx[(size_t)M_ROWS * DDIM];
__device__ __align__(256) int8_t g_qw[(size_t)N_ROWS * DDIM];
__device__ float g_sa[M_ROWS];
__device__ float g_sw[N_ROWS];

__device__ __forceinline__ uint32_t smem_u32(const void* p) {
    uint32_t a;
    asm("{ .reg .u64 t; cvta.to.shared.u64 t, %1; cvt.u32.u64 %0, t; }" : "=r"(a) : "l"(p));
    return a;
}
__device__ __forceinline__ void cp4(uint32_t dst, const void* src) {
    asm volatile("cp.async.ca.shared.global [%0], [%1], 4;" :: "r"(dst), "l"(src) : "memory");
}
#define CP_COMMIT()  asm volatile("cp.async.commit_group;" ::: "memory")
#define CP_WAIT(n)   asm volatile("cp.async.wait_group %0;" :: "n"(n) : "memory")

__device__ __forceinline__ void imma16832(int* c, const uint32_t* a, const uint32_t* b) {
    asm volatile(
        "mma.sync.aligned.m16n8k32.row.col.s32.s8.s8.s32 "
        "{%0,%1,%2,%3}, {%4,%5,%6,%7}, {%8,%9}, {%0,%1,%2,%3};\n"
        : "+r"(c[0]), "+r"(c[1]), "+r"(c[2]), "+r"(c[3])
        : "r"(a[0]), "r"(a[1]), "r"(a[2]), "r"(a[3]), "r"(b[0]), "r"(b[1]));
}

// ---------------- fused row-wise absmax int8 quantization ----------------
__global__ __launch_bounds__(256) void quant_fused_kernel(
    const float* __restrict__ x, const float* __restrict__ w,
    const float* __restrict__ scales)
{
    const int b    = blockIdx.x;
    const bool isx = (b < M_ROWS);
    const int row  = isx ? b : (b - M_ROWS);
    const int tid  = threadIdx.x;
    const float4* src4 = reinterpret_cast<const float4*>((isx ? x : w) + (size_t)row * DDIM);
    const float4* scl4 = reinterpret_cast<const float4*>(scales);

    float v[16];
    float m = 0.f;
    #pragma unroll
    for (int i = 0; i < 4; i++) {
        int g = i * 256 + tid;
        float4 xv = src4[g];
        float4 s  = scl4[g];
        float t0, t1, t2, t3;
        if (isx) { t0 = xv.x * s.x; t1 = xv.y * s.y; t2 = xv.z * s.z; t3 = xv.w * s.w; }
        else     { t0 = xv.x / s.x; t1 = xv.y / s.y; t2 = xv.z / s.z; t3 = xv.w / s.w; }
        v[i*4+0] = t0; v[i*4+1] = t1; v[i*4+2] = t2; v[i*4+3] = t3;
        m = fmaxf(m, fmaxf(fmaxf(fabsf(t0), fabsf(t1)), fmaxf(fabsf(t2), fabsf(t3))));
    }

    __shared__ float red[8];
    #pragma unroll
    for (int o = 16; o > 0; o >>= 1)
        m = fmaxf(m, __shfl_xor_sync(0xffffffffu, m, o));
    if ((tid & 31) == 0) red[tid >> 5] = m;
    __syncthreads();
    if (tid < 32) {
        float t = (tid < 8) ? red[tid] : 0.f;
        #pragma unroll
        for (int o = 4; o > 0; o >>= 1)
            t = fmaxf(t, __shfl_xor_sync(0xffffffffu, t, o));
        if (tid == 0) red[0] = fmaxf(t, 1e-8f);
    }
    __syncthreads();
    const float absmax = red[0];
    const float qs = 127.f / absmax;

    int* qrow = reinterpret_cast<int*>((isx ? g_qx : g_qw) + (size_t)row * DDIM);
    #pragma unroll
    for (int i = 0; i < 4; i++) {
        int g = i * 256 + tid;
        int packed = 0;
        #pragma unroll
        for (int j = 0; j < 4; j++) {
            float t = rintf(v[i*4+j] * qs);
            t = fminf(fmaxf(t, -127.f), 127.f);
            packed |= ((int)t & 0xff) << (8 * j);
        }
        qrow[g] = packed;
    }
    if (tid == 0) {
        if (isx) g_sa[row] = absmax * (1.f / 127.f);
        else     g_sw[row] = absmax * (1.f / 127.f);
    }
}

// ---------------- hybrid GEMM, latency-pipelined fragments ----------------
// CTA 128x128; shared transposed tiles [ki][row], stride 136 ints; 4-stage ring,
// one __syncthreads per chunk. dp4a warps (n 0-63): 2-deep rolling fragment
// buffer. IMMA warps (n 64-127): all fragments for both k32 steps loaded
// up-front each chunk (single batched latency exposure, then 32 IMMAs).
#define NCHUNK (KINT / 16)       // 64
#define TSTR   136
#define STAGE_I (16 * TSTR)
#define NSTG   4
#define SMEM_BYTES (NSTG * 2 * STAGE_I * 4)   // 69632

__global__ __launch_bounds__(256, 2) void gemm_hybrid_kernel(
    const float* __restrict__ bias, const float* __restrict__ scales,
    float* __restrict__ out)
{
    extern __shared__ int smem[];
    int* As = smem;                       // [4][16][TSTR]
    int* Bs = smem + NSTG * STAGE_I;      // [4][16][TSTR]

    const int tid  = threadIdx.x;
    const int wid  = tid >> 5;
    const int lane = tid & 31;
    const int m0   = blockIdx.y * 128;
    const int n0   = blockIdx.x * 128;

    const int* qxi = reinterpret_cast<const int*>(g_qx);
    const int* qwi = reinterpret_cast<const int*>(g_qw);
    const uint32_t aBase = smem_u32(As);
    const uint32_t bBase = smem_u32(Bs);

    auto load_stage = [&](int c) {
        const int s = c & 3;
        #pragma unroll
        for (int j = 0; j < 8; j++) {
            int idx = j * 256 + tid;          // 0..2047
            int m = idx >> 4, ki = idx & 15;
            uint32_t d = (uint32_t)((s * 16 + ki) * TSTR + m) * 4;
            cp4(aBase + d, qxi + (size_t)(m0 + m) * KINT + c * 16 + ki);
            cp4(bBase + d, qwi + (size_t)(n0 + m) * KINT + c * 16 + ki);
        }
    };

    if (wid < 4) {
        // ================= dp4a half: n in [0,64) =================
        const int ty = tid >> 3;
        const int tx = tid & 7;
        int acc[8][8];
        #pragma unroll
        for (int i = 0; i < 8; i++)
            #pragma unroll
            for (int j = 0; j < 8; j++) acc[i][j] = 0;

        load_stage(0); CP_COMMIT();
        load_stage(1); CP_COMMIT();
        load_stage(2); CP_COMMIT();
        int fa[2][8], fbv[2][8];                    // rolling fragment buffers
        for (int c = 0; c < NCHUNK; c++) {
            CP_WAIT(2);
            __syncthreads();
            if (c + 3 < NCHUNK) load_stage(c + 3);
            CP_COMMIT();
            const int sO = (c & 3) * 16;
            // preload ki=0 fragments
            {
                const int* ar = As + sO * TSTR;
                const int* br = Bs + sO * TSTR;
                *reinterpret_cast<int4*>(&fa[0][0]) = *reinterpret_cast<const int4*>(ar + ty * 8);
                *reinterpret_cast<int4*>(&fa[0][4]) = *reinterpret_cast<const int4*>(ar + ty * 8 + 4);
                *reinterpret_cast<int4*>(&fbv[0][0]) = *reinterpret_cast<const int4*>(br + tx * 8);
                *reinterpret_cast<int4*>(&fbv[0][4]) = *reinterpret_cast<const int4*>(br + tx * 8 + 4);
            }
            #pragma unroll
            for (int ki = 0; ki < 16; ki++) {
                const int cur = ki & 1, nxt = cur ^ 1;
                if (ki < 15) {
                    const int* ar = As + (sO + ki + 1) * TSTR;
                    const int* br = Bs + (sO + ki + 1) * TSTR;
                    *reinterpret_cast<int4*>(&fa[nxt][0]) = *reinterpret_cast<const int4*>(ar + ty * 8);
                    *reinterpret_cast<int4*>(&fa[nxt][4]) = *reinterpret_cast<const int4*>(ar + ty * 8 + 4);
                    *reinterpret_cast<int4*>(&fbv[nxt][0]) = *reinterpret_cast<const int4*>(br + tx * 8);
                    *reinterpret_cast<int4*>(&fbv[nxt][4]) = *reinterpret_cast<const int4*>(br + tx * 8 + 4);
                }
                #pragma unroll
                for (int i = 0; i < 8; i++)
                    #pragma unroll
                    for (int j = 0; j < 8; j++)
                        acc[i][j] = __dp4a(fa[cur][i], fbv[cur][j], acc[i][j]);
            }
        }

        float fw[8], fb[8];
        #pragma unroll
        for (int j = 0; j < 8; j++) {
            int n = n0 + tx * 8 + j;
            fw[j] = g_sw[n];
            fb[j] = __ldg(&bias[n]) / __ldg(&scales[n]);
        }
        #pragma unroll
        for (int i = 0; i < 8; i++) {
            int m = m0 + ty * 8 + i;
            float fav = g_sa[m];
            float4 o0, o1;
            o0.x = acc[i][0]*fav*fw[0]+fb[0]; o0.y = acc[i][1]*fav*fw[1]+fb[1];
            o0.z = acc[i][2]*fav*fw[2]+fb[2]; o0.w = acc[i][3]*fav*fw[3]+fb[3];
            o1.x = acc[i][4]*fav*fw[4]+fb[4]; o1.y = acc[i][5]*fav*fw[5]+fb[5];
            o1.z = acc[i][6]*fav*fw[6]+fb[6]; o1.w = acc[i][7]*fav*fw[7]+fb[7];
            float4* orow = reinterpret_cast<float4*>(out + (size_t)m * N_ROWS + n0 + tx * 8);
            orow[0] = o0; orow[1] = o1;
        }
    } else {
        // ================= IMMA half: n in [64,128) =================
        const int wi  = wid - 4;
        const int wm  = wi >> 1;
        const int wn  = wi & 1;
        const int g   = lane >> 2;
        const int tig = lane & 3;
        int acc[4][4][4];
        #pragma unroll
        for (int i = 0; i < 4; i++)
            #pragma unroll
            for (int j = 0; j < 4; j++)
                #pragma unroll
                for (int k = 0; k < 4; k++) acc[i][j][k] = 0;

        load_stage(0); CP_COMMIT();
        load_stage(1); CP_COMMIT();
        load_stage(2); CP_COMMIT();
        for (int c = 0; c < NCHUNK; c++) {
            CP_WAIT(2);
            __syncthreads();
            if (c + 3 < NCHUNK) load_stage(c + 3);
            CP_COMMIT();
            const int sO = (c & 3) * 16;
            // batch-load ALL fragments for both k32 steps (12 rows x loads in flight)
            uint32_t a[2][4][4], b[2][4][2];
            #pragma unroll
            for (int ks = 0; ks < 2; ks++) {
                const int* klor = As + (sO + ks * 8 + tig) * TSTR;
                const int* khir = As + (sO + ks * 8 + tig + 4) * TSTR;
                const int* klob = Bs + (sO + ks * 8 + tig) * TSTR;
                const int* khib = Bs + (sO + ks * 8 + tig + 4) * TSTR;
                #pragma unroll
                for (int mt = 0; mt < 4; mt++) {
                    int r = wm * 64 + mt * 16 + g;
                    a[ks][mt][0] = (uint32_t)klor[r];
                    a[ks][mt][1] = (uint32_t)klor[r + 8];
                    a[ks][mt][2] = (uint32_t)khir[r];
                    a[ks][mt][3] = (uint32_t)khir[r + 8];
                }
                #pragma unroll
                for (int nt = 0; nt < 4; nt++) {
                    int n = 64 + wn * 32 + nt * 8 + g;
                    b[ks][nt][0] = (uint32_t)klob[n];
                    b[ks][nt][1] = (uint32_t)khib[n];
                }
            }
            #pragma unroll
            for (int ks = 0; ks < 2; ks++)
                #pragma unroll
                for (int mt = 0; mt < 4; mt++)
                    #pragma unroll
                    for (int nt = 0; nt < 4; nt++)
                        imma16832(acc[mt][nt], a[ks][mt], b[ks][nt]);
        }

        float fw[4][2], fb[4][2];
        #pragma unroll
        for (int nt = 0; nt < 4; nt++) {
            int n = n0 + 64 + wn * 32 + nt * 8 + 2 * tig;
            fw[nt][0] = g_sw[n];
            fw[nt][1] = g_sw[n + 1];
            fb[nt][0] = __ldg(&bias[n])     / __ldg(&scales[n]);
            fb[nt][1] = __ldg(&bias[n + 1]) / __ldg(&scales[n + 1]);
        }
        #pragma unroll
        for (int mt = 0; mt < 4; mt++) {
            int mA = m0 + wm * 64 + mt * 16 + g;
            float saA = g_sa[mA];
            float saB = g_sa[mA + 8];
            #pragma unroll
            for (int nt = 0; nt < 4; nt++) {
                int n = n0 + 64 + wn * 32 + nt * 8 + 2 * tig;
                float2 o0, o1;
                o0.x = acc[mt][nt][0] * saA * fw[nt][0] + fb[nt][0];
                o0.y = acc[mt][nt][1] * saA * fw[nt][1] + fb[nt][1];
                o1.x = acc[mt][nt][2] * saB * fw[nt][0] + fb[nt][0];
                o1.y = acc[mt][nt][3] * saB * fw[nt][1] + fb[nt][1];
                *reinterpret_cast<float2*>(out + (size_t)mA       * N_ROWS + n) = o0;
                *reinterpret_cast<float2*>(out + (size_t)(mA + 8) * N_ROWS + n) = o1;
            }
        }
    }
}

// ---------------- launch ----------------
extern "C" void kernel_launch(void* const* d_in, const int* in_sizes, int n_in,
                              void* d_out, int out_size)
{
    const float* x      = (const float*)d_in[0];
    const float* weight = (const float*)d_in[1];
    const float* bias   = (const float*)d_in[2];
    const float* scales = (const float*)d_in[3];
    float* out = (float*)d_out;

    cudaFuncSetAttribute(gemm_hybrid_kernel,
                         cudaFuncAttributeMaxDynamicSharedMemorySize, SMEM_BYTES);

    quant_fused_kernel<<<M_ROWS + N_ROWS, 256>>>(x, weight, scales);

    dim3 grid(N_ROWS / 128, M_ROWS / 128);   // (32, 64)
    gemm_hybrid_kernel<<<grid, 256, SMEM_BYTES>>>(bias, scales, out);
}